// round 13
// baseline (speedup 1.0000x reference)
#include <cuda_runtime.h>
#include <cuda_fp16.h>
#include <math.h>
#include <stdint.h>

#define SEQ   2048
#define BATCH 2
#define NTOK  4096
#define HID   896
#define NH    14
#define NKV   2
#define HD    64
#define NGRP  7
#define KD    896
#define KITERS (KD/32)       // 28
#define NQT   (SEQ/64)       // 32 q-tiles per sequence
#define LOG2E 1.4426950408889634f

// ---------------- scratch (allocation-free rule) ----------------------------
__device__ __half g_xh [NTOK*HID];
__device__ __half g_q  [NTOK*NH*HD];
__device__ __half g_k  [NTOK*NKV*HD];
__device__ __half g_v  [NTOK*NKV*HD];
__device__ __half g_att[NTOK*NH*HD];
__device__ __half g_wq [NH*HD*HID];    // W^T [N][K] fp16
__device__ __half g_wk [NKV*HD*HID];
__device__ __half g_wv [NKV*HD*HID];
__device__ __half g_wo [HID*HID];
__device__ float  g_zero[HID];

// ---------------- helpers ---------------------------------------------------
__device__ __forceinline__ uint32_t cvta_smem(const void* p) {
    uint32_t a;
    asm("{ .reg .u64 t; cvta.to.shared.u64 t, %1; cvt.u32.u64 %0, t; }"
        : "=r"(a) : "l"(p));
    return a;
}
__device__ __forceinline__ void ldsm4(uint32_t* r, uint32_t addr) {
    asm volatile("ldmatrix.sync.aligned.m8n8.x4.shared.b16 {%0,%1,%2,%3}, [%4];"
        : "=r"(r[0]), "=r"(r[1]), "=r"(r[2]), "=r"(r[3]) : "r"(addr));
}
__device__ __forceinline__ void ldsm4t(uint32_t* r, uint32_t addr) {
    asm volatile("ldmatrix.sync.aligned.m8n8.x4.trans.shared.b16 {%0,%1,%2,%3}, [%4];"
        : "=r"(r[0]), "=r"(r[1]), "=r"(r[2]), "=r"(r[3]) : "r"(addr));
}
__device__ __forceinline__ void mma16(float* c, const uint32_t* a, const uint32_t* b) {
    asm volatile("mma.sync.aligned.m16n8k16.row.col.f32.f16.f16.f32 "
        "{%0,%1,%2,%3}, {%4,%5,%6,%7}, {%8,%9}, {%0,%1,%2,%3};"
        : "+f"(c[0]), "+f"(c[1]), "+f"(c[2]), "+f"(c[3])
        : "r"(a[0]), "r"(a[1]), "r"(a[2]), "r"(a[3]), "r"(b[0]), "r"(b[1]));
}
__device__ __forceinline__ float fexp2(float x) {
    float y;
    asm("ex2.approx.f32 %0, %1;" : "=f"(y) : "f"(x));
    return y;
}
__device__ __forceinline__ uint32_t h2u(float x, float y) {
    __half2 h = __floats2half2_rn(x, y);
    return *(uint32_t*)&h;
}

// ---------------- prep kernels ----------------------------------------------
__global__ void conv_x_kernel(const float* __restrict__ src, __half* __restrict__ dst, int n) {
    int i = blockIdx.x * blockDim.x + threadIdx.x;
    if (i < n) dst[i] = __float2half_rn(src[i]);
}

__global__ void conv_wT_all(const float* __restrict__ Wq, const float* __restrict__ Wk,
                            const float* __restrict__ Wv, const float* __restrict__ Wo,
                            __half* __restrict__ wq, __half* __restrict__ wk,
                            __half* __restrict__ wv, __half* __restrict__ wo) {
    const float* W; __half* Wt; int N;
    switch (blockIdx.z) {
        case 0:  W = Wq; Wt = wq; N = NH*HD;  break;
        case 1:  W = Wk; Wt = wk; N = NKV*HD; break;
        case 2:  W = Wv; Wt = wv; N = NKV*HD; break;
        default: W = Wo; Wt = wo; N = HID;    break;
    }
    if ((int)(blockIdx.y * 32) >= N) return;
    __shared__ float t[32][33];
    int k0 = blockIdx.x * 32, n0 = blockIdx.y * 32;
    int tx = threadIdx.x, ty = threadIdx.y;   // 32 x 8
#pragma unroll
    for (int i = ty; i < 32; i += 8) t[i][tx] = W[(size_t)(k0 + i) * N + n0 + tx];
    __syncthreads();
#pragma unroll
    for (int i = ty; i < 32; i += 8)
        Wt[(size_t)(n0 + i) * KD + k0 + tx] = __float2half_rn(t[tx][i]);
}

// ---------------- fp16 mma GEMM (2-stage) -----------------------------------
// rope_mode: 0 = none (fp32 out), 1 = q (rope + 0.125*log2e), 2 = k, 3 = plain fp16
#define GP 40

__device__ __forceinline__ void gemm_body_h(
    const __half* __restrict__ A, const __half* __restrict__ Wt,
    const float* __restrict__ bias,
    __half* __restrict__ Ch, float* __restrict__ Cf,
    int N, int colBase, int rope_mode)
{
    __shared__ __half As[2][128*GP];
    __shared__ __half Bs[2][128*GP];

    const int tid  = threadIdx.x;
    const int lane = tid & 31, wid = tid >> 5;
    const int wrow = (wid >> 1) * 32, wcol = (wid & 1) * 64;
    const int rowBase = blockIdx.y * 128;
    const int m4 = lane >> 3, l7 = lane & 7;

    uint32_t sA[2] = { cvta_smem(As[0]), cvta_smem(As[1]) };
    uint32_t sB[2] = { cvta_smem(Bs[0]), cvta_smem(Bs[1]) };

    auto load = [&](int it) {
        int buf = it & 1, k0 = it * 32;
#pragma unroll
        for (int p = 0; p < 2; p++) {
            int id = tid + p * 256;
            int row = id >> 2, c = id & 3;
            const __half* srcA = A  + (size_t)(rowBase + row) * KD + k0 + c * 8;
            const __half* srcB = Wt + (size_t)(colBase + row) * KD + k0 + c * 8;
            uint32_t off = (row * GP + c * 8) * 2;
            asm volatile("cp.async.cg.shared.global [%0], [%1], 16;" :: "r"(sA[buf] + off), "l"(srcA));
            asm volatile("cp.async.cg.shared.global [%0], [%1], 16;" :: "r"(sB[buf] + off), "l"(srcB));
        }
        asm volatile("cp.async.commit_group;" ::: "memory");
    };

    float acc[2][8][4];
#pragma unroll
    for (int mi = 0; mi < 2; mi++)
#pragma unroll
        for (int ni = 0; ni < 8; ni++)
#pragma unroll
            for (int t = 0; t < 4; t++) acc[mi][ni][t] = 0.f;

    load(0); load(1);

    for (int it = 0; it < KITERS; it++) {
        int buf = it & 1;
        if (it < KITERS - 1) asm volatile("cp.async.wait_group 1;" ::: "memory");
        else                 asm volatile("cp.async.wait_group 0;" ::: "memory");
        __syncthreads();

#pragma unroll
        for (int ks = 0; ks < 2; ks++) {
            uint32_t a[2][4];
#pragma unroll
            for (int mi = 0; mi < 2; mi++)
                ldsm4(a[mi], sA[buf] +
                    ((wrow + mi*16 + (m4 & 1)*8 + l7) * GP + (ks*2 + (m4 >> 1)) * 8) * 2);
#pragma unroll
            for (int p = 0; p < 4; p++) {
                uint32_t b[4];
                ldsm4(b, sB[buf] +
                    ((wcol + p*16 + (m4 >> 1)*8 + l7) * GP + (ks*2 + (m4 & 1)) * 8) * 2);
                mma16(acc[0][2*p],   a[0], b);
                mma16(acc[0][2*p+1], a[0], b + 2);
                mma16(acc[1][2*p],   a[1], b);
                mma16(acc[1][2*p+1], a[1], b + 2);
            }
        }
        __syncthreads();
        if (it + 2 < KITERS) load(it + 2);
    }

    if (rope_mode == 1 || rope_mode == 2) {
        const float scale = (rope_mode == 1) ? 0.125f * LOG2E : 1.0f;
#pragma unroll
        for (int mi = 0; mi < 2; mi++) {
            int r0 = rowBase + wrow + mi*16 + (lane >> 2);
            float s0 = (float)(r0 & (SEQ-1));
            float s1 = (float)((r0 + 8) & (SEQ-1));
#pragma unroll
            for (int ni = 0; ni < 4; ni++) {
                int cl = colBase + wcol + ni*8 + 2*(lane & 3);
                int ch = cl + 32;
                float x0 = acc[mi][ni][0]   + bias[cl];
                float x1 = acc[mi][ni][1]   + bias[cl+1];
                float x2 = acc[mi][ni][2]   + bias[cl];
                float x3 = acc[mi][ni][3]   + bias[cl+1];
                float y0 = acc[mi][ni+4][0] + bias[ch];
                float y1 = acc[mi][ni+4][1] + bias[ch+1];
                float y2 = acc[mi][ni+4][2] + bias[ch];
                float y3 = acc[mi][ni+4][3] + bias[ch+1];
                int dd = (cl & 63);
                float inv0 = powf(1.0e6f, -(float)dd     * (1.0f/32.0f));
                float inv1 = powf(1.0e6f, -(float)(dd+1) * (1.0f/32.0f));
                float c00, sn00, c01, sn01, c10, sn10, c11, sn11;
                sincosf(s0 * inv0, &sn00, &c00);
                sincosf(s0 * inv1, &sn01, &c01);
                sincosf(s1 * inv0, &sn10, &c10);
                sincosf(s1 * inv1, &sn11, &c11);
                float lo0 = (x0*c00 - y0*sn00) * scale, hi0 = (y0*c00 + x0*sn00) * scale;
                float lo1 = (x1*c01 - y1*sn01) * scale, hi1 = (y1*c01 + x1*sn01) * scale;
                float lo2 = (x2*c10 - y2*sn10) * scale, hi2 = (y2*c10 + x2*sn10) * scale;
                float lo3 = (x3*c11 - y3*sn11) * scale, hi3 = (y3*c11 + x3*sn11) * scale;
                *(__half2*)&Ch[(size_t)r0     * N + cl] = __floats2half2_rn(lo0, lo1);
                *(__half2*)&Ch[(size_t)r0     * N + ch] = __floats2half2_rn(hi0, hi1);
                *(__half2*)&Ch[(size_t)(r0+8) * N + cl] = __floats2half2_rn(lo2, lo3);
                *(__half2*)&Ch[(size_t)(r0+8) * N + ch] = __floats2half2_rn(hi2, hi3);
            }
        }
        return;
    }

#pragma unroll
    for (int mi = 0; mi < 2; mi++) {
        int r0 = rowBase + wrow + mi*16 + (lane >> 2);
#pragma unroll
        for (int ni = 0; ni < 8; ni++) {
            int c = colBase + wcol + ni*8 + 2*(lane & 3);
            float v0 = acc[mi][ni][0] + bias[c];
            float v1 = acc[mi][ni][1] + bias[c+1];
            float v2 = acc[mi][ni][2] + bias[c];
            float v3 = acc[mi][ni][3] + bias[c+1];
            if (Ch) {
                *(__half2*)&Ch[(size_t)r0 * N + c]     = __floats2half2_rn(v0, v1);
                *(__half2*)&Ch[(size_t)(r0+8) * N + c] = __floats2half2_rn(v2, v3);
            } else {
                *(float2*)&Cf[(size_t)r0 * N + c]     = make_float2(v0, v1);
                *(float2*)&Cf[(size_t)(r0+8) * N + c] = make_float2(v2, v3);
            }
        }
    }
}

__global__ void __launch_bounds__(256) gemm_qkv_kernel(
    const __half* __restrict__ X,
    const __half* __restrict__ wq, const __half* __restrict__ wk, const __half* __restrict__ wv,
    const float* __restrict__ bq, const float* __restrict__ bk, const float* __restrict__ bv,
    __half* __restrict__ q, __half* __restrict__ k, __half* __restrict__ v)
{
    int bx = blockIdx.x;
    if (bx < 7)       gemm_body_h(X, wq, bq, q, nullptr, NH*HD,  bx*128, 1);
    else if (bx == 7) gemm_body_h(X, wk, bk, k, nullptr, NKV*HD, 0,      2);
    else              gemm_body_h(X, wv, bv, v, nullptr, NKV*HD, 0,      3);
}

__global__ void __launch_bounds__(256) gemm_o_kernel(
    const __half* __restrict__ A, const __half* __restrict__ W,
    const float* __restrict__ bias, float* __restrict__ C)
{
    gemm_body_h(A, W, bias, nullptr, C, HID, blockIdx.x * 128, 0);
}

// ---------------- flash attention: register-P FA2 path ----------------------
#define AP 72
#define ATILE (64*AP)
#define ATT_SMEM (5*ATILE*2)  // Q, K0, K1, V0, V1 = 46080 B

__global__ void __launch_bounds__(128) attn_kernel(
    const __half* __restrict__ Q, const __half* __restrict__ K,
    const __half* __restrict__ V, __half* __restrict__ O)
{
    extern __shared__ __half sh[];
    uint32_t smb = cvta_smem(sh);

    // longest-first dispatch: low blockIdx.x (issued earliest) -> largest qt
    const int qt = NQT - 1 - blockIdx.x;
    const int bh = blockIdx.y;
    const int b  = bh / NH, h = bh % NH, kvh = h / NGRP;

    const int tid = threadIdx.x;
    const int lane = tid & 31, wid = tid >> 5;
    const int rw = wid * 16;
    const int rloc = rw + (lane >> 2);
    const int m4 = lane >> 3, l7 = lane & 7;
    const int tokQ = b * SEQ + qt * 64;

    // Q tile load (own commit group)
#pragma unroll
    for (int p = 0; p < 4; p++) {
        int id = tid + p * 128;
        int row = id >> 3, c = id & 7;
        const __half* src = Q + (size_t)(tokQ + row) * (NH*HD) + h*HD + c*8;
        asm volatile("cp.async.cg.shared.global [%0], [%1], 16;"
                     :: "r"(smb + (row * AP + c*8) * 2), "l"(src));
    }
    asm volatile("cp.async.commit_group;" ::: "memory");

    auto loadKV = [&](int kt) {
        int buf = kt & 1;
        int tokK = b * SEQ + kt * 64;
        uint32_t kb = smb + (1 + buf) * ATILE * 2;
        uint32_t vb = smb + (3 + buf) * ATILE * 2;
#pragma unroll
        for (int p = 0; p < 4; p++) {
            int id = tid + p * 128;
            int row = id >> 3, c = id & 7;
            const __half* ks = K + (size_t)(tokK + row) * (NKV*HD) + kvh*HD + c*8;
            const __half* vs = V + (size_t)(tokK + row) * (NKV*HD) + kvh*HD + c*8;
            uint32_t off = (row * AP + c*8) * 2;
            asm volatile("cp.async.cg.shared.global [%0], [%1], 16;" :: "r"(kb + off), "l"(ks));
            asm volatile("cp.async.cg.shared.global [%0], [%1], 16;" :: "r"(vb + off), "l"(vs));
        }
        asm volatile("cp.async.commit_group;" ::: "memory");
    };
    loadKV(0);

    // hoist Q fragments to registers (reused every kt iteration)
    uint32_t qa[4][4];
    asm volatile("cp.async.wait_group 1;" ::: "memory");   // Q group done
    __syncthreads();
#pragma unroll
    for (int ks = 0; ks < 4; ks++)
        ldsm4(qa[ks], smb + ((rw + (m4 & 1)*8 + l7) * AP + (ks*2 + (m4 >> 1)) * 8) * 2);

    float m0 = -1e30f, m1 = -1e30f, l0 = 0.f, l1 = 0.f;
    float o[8][4];
#pragma unroll
    for (int di = 0; di < 8; di++)
#pragma unroll
        for (int t = 0; t < 4; t++) o[di][t] = 0.f;

    for (int kt = 0; kt <= qt; kt++) {
        int buf = kt & 1;
        if (kt < qt) loadKV(kt + 1);
        if (kt < qt) asm volatile("cp.async.wait_group 1;" ::: "memory");
        else         asm volatile("cp.async.wait_group 0;" ::: "memory");
        __syncthreads();

        const uint32_t kbase = smb + (1 + buf) * ATILE * 2;
        const uint32_t vbase = smb + (3 + buf) * ATILE * 2;

        // ---- S = Q @ K^T (log2e/8 pre-folded into Q) ----
        float s[8][4];
#pragma unroll
        for (int ni = 0; ni < 8; ni++)
#pragma unroll
            for (int t = 0; t < 4; t++) s[ni][t] = 0.f;
#pragma unroll
        for (int ks = 0; ks < 4; ks++) {
#pragma unroll
            for (int p = 0; p < 4; p++) {
                uint32_t bf[4];
                ldsm4(bf, kbase + ((p*16 + (m4 >> 1)*8 + l7) * AP + (ks*2 + (m4 & 1)) * 8) * 2);
                mma16(s[2*p],   qa[ks], bf);
                mma16(s[2*p+1], qa[ks], bf + 2);
            }
        }

        if (kt == qt) {
#pragma unroll
            for (int ni = 0; ni < 8; ni++) {
                int c = ni*8 + 2*(lane & 3);
                if (c     > rloc)     s[ni][0] = -1e30f;
                if (c + 1 > rloc)     s[ni][1] = -1e30f;
                if (c     > rloc + 8) s[ni][2] = -1e30f;
                if (c + 1 > rloc + 8) s[ni][3] = -1e30f;
            }
        }

        // ---- online softmax (base-2) ----
        float mx0 = -1e30f, mx1 = -1e30f;
#pragma unroll
        for (int ni = 0; ni < 8; ni++) {
            mx0 = fmaxf(mx0, fmaxf(s[ni][0], s[ni][1]));
            mx1 = fmaxf(mx1, fmaxf(s[ni][2], s[ni][3]));
        }
        mx0 = fmaxf(mx0, __shfl_xor_sync(0xffffffffu, mx0, 1));
        mx0 = fmaxf(mx0, __shfl_xor_sync(0xffffffffu, mx0, 2));
        mx1 = fmaxf(mx1, __shfl_xor_sync(0xffffffffu, mx1, 1));
        mx1 = fmaxf(mx1, __shfl_xor_sync(0xffffffffu, mx1, 2));
        float nm0 = fmaxf(m0, mx0), nm1 = fmaxf(m1, mx1);
        float a0 = fexp2(m0 - nm0), a1 = fexp2(m1 - nm1);
        m0 = nm0; m1 = nm1;
        float sum0 = 0.f, sum1 = 0.f;
#pragma unroll
        for (int ni = 0; ni < 8; ni++) {
            s[ni][0] = fexp2(s[ni][0] - nm0);
            s[ni][1] = fexp2(s[ni][1] - nm0);
            s[ni][2] = fexp2(s[ni][2] - nm1);
            s[ni][3] = fexp2(s[ni][3] - nm1);
            sum0 += s[ni][0] + s[ni][1];
            sum1 += s[ni][2] + s[ni][3];
        }
        sum0 += __shfl_xor_sync(0xffffffffu, sum0, 1);
        sum0 += __shfl_xor_sync(0xffffffffu, sum0, 2);
        sum1 += __shfl_xor_sync(0xffffffffu, sum1, 1);
        sum1 += __shfl_xor_sync(0xffffffffu, sum1, 2);
        l0 = l0 * a0 + sum0;
        l1 = l1 * a1 + sum1;
#pragma unroll
        for (int di = 0; di < 8; di++) {
            o[di][0] *= a0; o[di][1] *= a0;
            o[di][2] *= a1; o[di][3] *= a1;
        }

        // ---- O += P @ V : P built in registers from S fragments ----
#pragma unroll
        for (int kj = 0; kj < 4; kj++) {
            uint32_t a[4];
            a[0] = h2u(s[2*kj][0],   s[2*kj][1]);
            a[1] = h2u(s[2*kj][2],   s[2*kj][3]);
            a[2] = h2u(s[2*kj+1][0], s[2*kj+1][1]);
            a[3] = h2u(s[2*kj+1][2], s[2*kj+1][3]);
#pragma unroll
            for (int p = 0; p < 4; p++) {
                uint32_t bf[4];
                ldsm4t(bf, vbase + ((kj*16 + (m4 & 1)*8 + l7) * AP + (p*2 + (m4 >> 1)) * 8) * 2);
                mma16(o[2*p],   a, bf);
                mma16(o[2*p+1], a, bf + 2);
            }
        }
        __syncthreads();
    }

    float i0 = 1.0f / l0, i1 = 1.0f / l1;
    int gr = tokQ + rloc;
#pragma unroll
    for (int di = 0; di < 8; di++) {
        int c = di*8 + 2*(lane & 3);
        *(__half2*)&O[(size_t)gr * (NH*HD) + h*HD + c] =
            __floats2half2_rn(o[di][0] * i0, o[di][1] * i0);
        *(__half2*)&O[(size_t)(gr + 8) * (NH*HD) + h*HD + c] =
            __floats2half2_rn(o[di][2] * i1, o[di][3] * i1);
    }
}

// ---------------- launch ----------------------------------------------------
extern "C" void kernel_launch(void* const* d_in, const int* in_sizes, int n_in,
                              void* d_out, int out_size) {
    const float* X  = (const float*)d_in[0];
    // d_in[1] = attention_mask: fixed causal mask -> analytic
    const float* Wq = (const float*)d_in[2];
    const float* bq = (const float*)d_in[3];
    const float* Wk = (const float*)d_in[4];
    const float* bk = (const float*)d_in[5];
    const float* Wv = (const float*)d_in[6];
    const float* bv = (const float*)d_in[7];
    const float* Wo = (const float*)d_in[8];
    float* out = (float*)d_out;

    __half *xh, *q, *k, *v, *att, *wq, *wk, *wv, *wo;
    float *zb;
    cudaGetSymbolAddress((void**)&xh,  g_xh);
    cudaGetSymbolAddress((void**)&q,   g_q);
    cudaGetSymbolAddress((void**)&k,   g_k);
    cudaGetSymbolAddress((void**)&v,   g_v);
    cudaGetSymbolAddress((void**)&att, g_att);
    cudaGetSymbolAddress((void**)&wq,  g_wq);
    cudaGetSymbolAddress((void**)&wk,  g_wk);
    cudaGetSymbolAddress((void**)&wv,  g_wv);
    cudaGetSymbolAddress((void**)&wo,  g_wo);
    cudaGetSymbolAddress((void**)&zb,  g_zero);

    // prep
    conv_x_kernel<<<(NTOK*HID + 255)/256, 256>>>(X, xh, NTOK*HID);
    conv_wT_all<<<dim3(KD/32, HID/32, 4), dim3(32,8)>>>(Wq, Wk, Wv, Wo, wq, wk, wv, wo);

    // fused QKV projection + RoPE epilogue (q scaled by 0.125*log2e)
    gemm_qkv_kernel<<<dim3(9, NTOK/128), 256>>>(xh, wq, wk, wv, bq, bk, bv, q, k, v);

    // attention: 896 single-tile CTAs, longest-first
    cudaFuncSetAttribute(attn_kernel, cudaFuncAttributeMaxDynamicSharedMemorySize, ATT_SMEM);
    attn_kernel<<<dim3(NQT, BATCH*NH), 128, ATT_SMEM>>>(q, k, v, att);

    // output projection
    gemm_o_kernel<<<dim3(HID/128, NTOK/128), 256>>>(att, wo, zb, out);
}

// round 14
// speedup vs baseline: 1.1825x; 1.1825x over previous
#include <cuda_runtime.h>
#include <cuda_fp16.h>
#include <math.h>
#include <stdint.h>

#define SEQ   2048
#define BATCH 2
#define NTOK  4096
#define HID   896
#define NH    14
#define NKV   2
#define HD    64
#define NGRP  7
#define KD    896
#define KITERS (KD/32)       // 28
#define NQT   (SEQ/64)       // 32 q-tiles per sequence
#define LOG2E 1.4426950408889634f

// ---------------- scratch (allocation-free rule) ----------------------------
__device__ __half g_xh [NTOK*HID];
__device__ __half g_q  [NTOK*NH*HD];
__device__ __half g_k  [NTOK*NKV*HD];
__device__ __half g_v  [NTOK*NKV*HD];
__device__ __half g_att[NTOK*NH*HD];
__device__ __half g_wq [NH*HD*HID];    // W^T [N][K] fp16
__device__ __half g_wk [NKV*HD*HID];
__device__ __half g_wv [NKV*HD*HID];
__device__ __half g_wo [HID*HID];
__device__ float  g_zero[HID];

// ---------------- helpers ---------------------------------------------------
__device__ __forceinline__ uint32_t cvta_smem(const void* p) {
    uint32_t a;
    asm("{ .reg .u64 t; cvta.to.shared.u64 t, %1; cvt.u32.u64 %0, t; }"
        : "=r"(a) : "l"(p));
    return a;
}
__device__ __forceinline__ void ldsm4(uint32_t* r, uint32_t addr) {
    asm volatile("ldmatrix.sync.aligned.m8n8.x4.shared.b16 {%0,%1,%2,%3}, [%4];"
        : "=r"(r[0]), "=r"(r[1]), "=r"(r[2]), "=r"(r[3]) : "r"(addr));
}
__device__ __forceinline__ void ldsm4t(uint32_t* r, uint32_t addr) {
    asm volatile("ldmatrix.sync.aligned.m8n8.x4.trans.shared.b16 {%0,%1,%2,%3}, [%4];"
        : "=r"(r[0]), "=r"(r[1]), "=r"(r[2]), "=r"(r[3]) : "r"(addr));
}
__device__ __forceinline__ void mma16(float* c, const uint32_t* a, const uint32_t* b) {
    asm volatile("mma.sync.aligned.m16n8k16.row.col.f32.f16.f16.f32 "
        "{%0,%1,%2,%3}, {%4,%5,%6,%7}, {%8,%9}, {%0,%1,%2,%3};"
        : "+f"(c[0]), "+f"(c[1]), "+f"(c[2]), "+f"(c[3])
        : "r"(a[0]), "r"(a[1]), "r"(a[2]), "r"(a[3]), "r"(b[0]), "r"(b[1]));
}
__device__ __forceinline__ float fexp2(float x) {
    float y;
    asm("ex2.approx.f32 %0, %1;" : "=f"(y) : "f"(x));
    return y;
}
__device__ __forceinline__ uint32_t h2u(float x, float y) {
    __half2 h = __floats2half2_rn(x, y);
    return *(uint32_t*)&h;
}

// ---------------- prep kernels ----------------------------------------------
__global__ void conv_x_kernel(const float* __restrict__ src, __half* __restrict__ dst, int n) {
    int i = blockIdx.x * blockDim.x + threadIdx.x;
    if (i < n) dst[i] = __float2half_rn(src[i]);
}

__global__ void conv_wT_all(const float* __restrict__ Wq, const float* __restrict__ Wk,
                            const float* __restrict__ Wv, const float* __restrict__ Wo,
                            __half* __restrict__ wq, __half* __restrict__ wk,
                            __half* __restrict__ wv, __half* __restrict__ wo) {
    const float* W; __half* Wt; int N;
    switch (blockIdx.z) {
        case 0:  W = Wq; Wt = wq; N = NH*HD;  break;
        case 1:  W = Wk; Wt = wk; N = NKV*HD; break;
        case 2:  W = Wv; Wt = wv; N = NKV*HD; break;
        default: W = Wo; Wt = wo; N = HID;    break;
    }
    if ((int)(blockIdx.y * 32) >= N) return;
    __shared__ float t[32][33];
    int k0 = blockIdx.x * 32, n0 = blockIdx.y * 32;
    int tx = threadIdx.x, ty = threadIdx.y;   // 32 x 8
#pragma unroll
    for (int i = ty; i < 32; i += 8) t[i][tx] = W[(size_t)(k0 + i) * N + n0 + tx];
    __syncthreads();
#pragma unroll
    for (int i = ty; i < 32; i += 8)
        Wt[(size_t)(n0 + i) * KD + k0 + tx] = __float2half_rn(t[tx][i]);
}

// ---------------- fp16 mma GEMM: CTA 64 x 128, 8 warps of 16x64 -------------
// rope_mode: 0 = none (fp32 out), 1 = q (rope + 0.125*log2e), 2 = k, 3 = plain fp16
#define GP 40

__device__ __forceinline__ void gemm_body_h(
    const __half* __restrict__ A, const __half* __restrict__ Wt,
    const float* __restrict__ bias,
    __half* __restrict__ Ch, float* __restrict__ Cf,
    int N, int colBase, int rope_mode)
{
    __shared__ __half As[2][64*GP];
    __shared__ __half Bs[2][128*GP];

    const int tid  = threadIdx.x;
    const int lane = tid & 31, wid = tid >> 5;
    const int wrow = (wid >> 1) * 16, wcol = (wid & 1) * 64;
    const int rowBase = blockIdx.y * 64;
    const int m4 = lane >> 3, l7 = lane & 7;

    uint32_t sA[2] = { cvta_smem(As[0]), cvta_smem(As[1]) };
    uint32_t sB[2] = { cvta_smem(Bs[0]), cvta_smem(Bs[1]) };

    auto load = [&](int it) {
        int buf = it & 1, k0 = it * 32;
        {   // A: 64 rows x 4 chunks = 256 transfers (1 per thread)
            int row = tid >> 2, c = tid & 3;
            const __half* srcA = A + (size_t)(rowBase + row) * KD + k0 + c * 8;
            uint32_t off = (row * GP + c * 8) * 2;
            asm volatile("cp.async.cg.shared.global [%0], [%1], 16;" :: "r"(sA[buf] + off), "l"(srcA));
        }
#pragma unroll
        for (int p = 0; p < 2; p++) {   // B: 128 rows x 4 chunks = 512 transfers
            int id = tid + p * 256;
            int row = id >> 2, c = id & 3;
            const __half* srcB = Wt + (size_t)(colBase + row) * KD + k0 + c * 8;
            uint32_t off = (row * GP + c * 8) * 2;
            asm volatile("cp.async.cg.shared.global [%0], [%1], 16;" :: "r"(sB[buf] + off), "l"(srcB));
        }
        asm volatile("cp.async.commit_group;" ::: "memory");
    };

    float acc[8][4];
#pragma unroll
    for (int ni = 0; ni < 8; ni++)
#pragma unroll
        for (int t = 0; t < 4; t++) acc[ni][t] = 0.f;

    load(0); load(1);

    for (int it = 0; it < KITERS; it++) {
        int buf = it & 1;
        if (it < KITERS - 1) asm volatile("cp.async.wait_group 1;" ::: "memory");
        else                 asm volatile("cp.async.wait_group 0;" ::: "memory");
        __syncthreads();

#pragma unroll
        for (int ks = 0; ks < 2; ks++) {
            uint32_t a[4];
            ldsm4(a, sA[buf] +
                ((wrow + (m4 & 1)*8 + l7) * GP + (ks*2 + (m4 >> 1)) * 8) * 2);
#pragma unroll
            for (int p = 0; p < 4; p++) {
                uint32_t b[4];
                ldsm4(b, sB[buf] +
                    ((wcol + p*16 + (m4 >> 1)*8 + l7) * GP + (ks*2 + (m4 & 1)) * 8) * 2);
                mma16(acc[2*p],   a, b);
                mma16(acc[2*p+1], a, b + 2);
            }
        }
        __syncthreads();
        if (it + 2 < KITERS) load(it + 2);
    }

    if (rope_mode == 1 || rope_mode == 2) {
        const float scale = (rope_mode == 1) ? 0.125f * LOG2E : 1.0f;
        int r0 = rowBase + wrow + (lane >> 2);
        float s0 = (float)(r0 & (SEQ-1));
        float s1 = (float)((r0 + 8) & (SEQ-1));
#pragma unroll
        for (int ni = 0; ni < 4; ni++) {
            int cl = colBase + wcol + ni*8 + 2*(lane & 3);
            int ch = cl + 32;
            float x0 = acc[ni][0]   + bias[cl];
            float x1 = acc[ni][1]   + bias[cl+1];
            float x2 = acc[ni][2]   + bias[cl];
            float x3 = acc[ni][3]   + bias[cl+1];
            float y0 = acc[ni+4][0] + bias[ch];
            float y1 = acc[ni+4][1] + bias[ch+1];
            float y2 = acc[ni+4][2] + bias[ch];
            float y3 = acc[ni+4][3] + bias[ch+1];
            int dd = (cl & 63);
            float inv0 = powf(1.0e6f, -(float)dd     * (1.0f/32.0f));
            float inv1 = powf(1.0e6f, -(float)(dd+1) * (1.0f/32.0f));
            float c00, sn00, c01, sn01, c10, sn10, c11, sn11;
            sincosf(s0 * inv0, &sn00, &c00);
            sincosf(s0 * inv1, &sn01, &c01);
            sincosf(s1 * inv0, &sn10, &c10);
            sincosf(s1 * inv1, &sn11, &c11);
            float lo0 = (x0*c00 - y0*sn00) * scale, hi0 = (y0*c00 + x0*sn00) * scale;
            float lo1 = (x1*c01 - y1*sn01) * scale, hi1 = (y1*c01 + x1*sn01) * scale;
            float lo2 = (x2*c10 - y2*sn10) * scale, hi2 = (y2*c10 + x2*sn10) * scale;
            float lo3 = (x3*c11 - y3*sn11) * scale, hi3 = (y3*c11 + x3*sn11) * scale;
            *(__half2*)&Ch[(size_t)r0     * N + cl] = __floats2half2_rn(lo0, lo1);
            *(__half2*)&Ch[(size_t)r0     * N + ch] = __floats2half2_rn(hi0, hi1);
            *(__half2*)&Ch[(size_t)(r0+8) * N + cl] = __floats2half2_rn(lo2, lo3);
            *(__half2*)&Ch[(size_t)(r0+8) * N + ch] = __floats2half2_rn(hi2, hi3);
        }
        return;
    }

    {
        int r0 = rowBase + wrow + (lane >> 2);
#pragma unroll
        for (int ni = 0; ni < 8; ni++) {
            int c = colBase + wcol + ni*8 + 2*(lane & 3);
            float v0 = acc[ni][0] + bias[c];
            float v1 = acc[ni][1] + bias[c+1];
            float v2 = acc[ni][2] + bias[c];
            float v3 = acc[ni][3] + bias[c+1];
            if (Ch) {
                *(__half2*)&Ch[(size_t)r0 * N + c]     = __floats2half2_rn(v0, v1);
                *(__half2*)&Ch[(size_t)(r0+8) * N + c] = __floats2half2_rn(v2, v3);
            } else {
                *(float2*)&Cf[(size_t)r0 * N + c]     = make_float2(v0, v1);
                *(float2*)&Cf[(size_t)(r0+8) * N + c] = make_float2(v2, v3);
            }
        }
    }
}

__global__ void __launch_bounds__(256) gemm_qkv_kernel(
    const __half* __restrict__ X,
    const __half* __restrict__ wq, const __half* __restrict__ wk, const __half* __restrict__ wv,
    const float* __restrict__ bq, const float* __restrict__ bk, const float* __restrict__ bv,
    __half* __restrict__ q, __half* __restrict__ k, __half* __restrict__ v)
{
    int bx = blockIdx.x;
    if (bx < 7)       gemm_body_h(X, wq, bq, q, nullptr, NH*HD,  bx*128, 1);
    else if (bx == 7) gemm_body_h(X, wk, bk, k, nullptr, NKV*HD, 0,      2);
    else              gemm_body_h(X, wv, bv, v, nullptr, NKV*HD, 0,      3);
}

__global__ void __launch_bounds__(256) gemm_o_kernel(
    const __half* __restrict__ A, const __half* __restrict__ W,
    const float* __restrict__ bias, float* __restrict__ C)
{
    gemm_body_h(A, W, bias, nullptr, C, HID, blockIdx.x * 128, 0);
}

// ---------------- flash attention: register-P FA2 path (R11) ----------------
#define AP 72
#define ATILE (64*AP)
#define ATT_SMEM (5*ATILE*2)  // Q, K0, K1, V0, V1 = 46080 B

__device__ __forceinline__ void attn_tile(
    const __half* __restrict__ Q, const __half* __restrict__ K,
    const __half* __restrict__ V, __half* __restrict__ O,
    uint32_t smb, int qt, int b, int h, int kvh)
{
    const int tid = threadIdx.x;
    const int lane = tid & 31, wid = tid >> 5;
    const int rw = wid * 16;
    const int rloc = rw + (lane >> 2);
    const int m4 = lane >> 3, l7 = lane & 7;
    const int tokQ = b * SEQ + qt * 64;

    // Q tile load (own commit group)
#pragma unroll
    for (int p = 0; p < 4; p++) {
        int id = tid + p * 128;
        int row = id >> 3, c = id & 7;
        const __half* src = Q + (size_t)(tokQ + row) * (NH*HD) + h*HD + c*8;
        asm volatile("cp.async.cg.shared.global [%0], [%1], 16;"
                     :: "r"(smb + (row * AP + c*8) * 2), "l"(src));
    }
    asm volatile("cp.async.commit_group;" ::: "memory");

    auto loadKV = [&](int kt) {
        int buf = kt & 1;
        int tokK = b * SEQ + kt * 64;
        uint32_t kb = smb + (1 + buf) * ATILE * 2;
        uint32_t vb = smb + (3 + buf) * ATILE * 2;
#pragma unroll
        for (int p = 0; p < 4; p++) {
            int id = tid + p * 128;
            int row = id >> 3, c = id & 7;
            const __half* ks = K + (size_t)(tokK + row) * (NKV*HD) + kvh*HD + c*8;
            const __half* vs = V + (size_t)(tokK + row) * (NKV*HD) + kvh*HD + c*8;
            uint32_t off = (row * AP + c*8) * 2;
            asm volatile("cp.async.cg.shared.global [%0], [%1], 16;" :: "r"(kb + off), "l"(ks));
            asm volatile("cp.async.cg.shared.global [%0], [%1], 16;" :: "r"(vb + off), "l"(vs));
        }
        asm volatile("cp.async.commit_group;" ::: "memory");
    };
    loadKV(0);

    // hoist Q fragments to registers
    uint32_t qa[4][4];
    asm volatile("cp.async.wait_group 1;" ::: "memory");
    __syncthreads();
#pragma unroll
    for (int ks = 0; ks < 4; ks++)
        ldsm4(qa[ks], smb + ((rw + (m4 & 1)*8 + l7) * AP + (ks*2 + (m4 >> 1)) * 8) * 2);

    float m0 = -1e30f, m1 = -1e30f, l0 = 0.f, l1 = 0.f;
    float o[8][4];
#pragma unroll
    for (int di = 0; di < 8; di++)
#pragma unroll
        for (int t = 0; t < 4; t++) o[di][t] = 0.f;

    for (int kt = 0; kt <= qt; kt++) {
        int buf = kt & 1;
        if (kt < qt) loadKV(kt + 1);
        if (kt < qt) asm volatile("cp.async.wait_group 1;" ::: "memory");
        else         asm volatile("cp.async.wait_group 0;" ::: "memory");
        __syncthreads();

        const uint32_t kbase = smb + (1 + buf) * ATILE * 2;
        const uint32_t vbase = smb + (3 + buf) * ATILE * 2;

        float s[8][4];
#pragma unroll
        for (int ni = 0; ni < 8; ni++)
#pragma unroll
            for (int t = 0; t < 4; t++) s[ni][t] = 0.f;
#pragma unroll
        for (int ks = 0; ks < 4; ks++) {
#pragma unroll
            for (int p = 0; p < 4; p++) {
                uint32_t bf[4];
                ldsm4(bf, kbase + ((p*16 + (m4 >> 1)*8 + l7) * AP + (ks*2 + (m4 & 1)) * 8) * 2);
                mma16(s[2*p],   qa[ks], bf);
                mma16(s[2*p+1], qa[ks], bf + 2);
            }
        }

        if (kt == qt) {
#pragma unroll
            for (int ni = 0; ni < 8; ni++) {
                int c = ni*8 + 2*(lane & 3);
                if (c     > rloc)     s[ni][0] = -1e30f;
                if (c + 1 > rloc)     s[ni][1] = -1e30f;
                if (c     > rloc + 8) s[ni][2] = -1e30f;
                if (c + 1 > rloc + 8) s[ni][3] = -1e30f;
            }
        }

        float mx0 = -1e30f, mx1 = -1e30f;
#pragma unroll
        for (int ni = 0; ni < 8; ni++) {
            mx0 = fmaxf(mx0, fmaxf(s[ni][0], s[ni][1]));
            mx1 = fmaxf(mx1, fmaxf(s[ni][2], s[ni][3]));
        }
        mx0 = fmaxf(mx0, __shfl_xor_sync(0xffffffffu, mx0, 1));
        mx0 = fmaxf(mx0, __shfl_xor_sync(0xffffffffu, mx0, 2));
        mx1 = fmaxf(mx1, __shfl_xor_sync(0xffffffffu, mx1, 1));
        mx1 = fmaxf(mx1, __shfl_xor_sync(0xffffffffu, mx1, 2));
        float nm0 = fmaxf(m0, mx0), nm1 = fmaxf(m1, mx1);
        float a0 = fexp2(m0 - nm0), a1 = fexp2(m1 - nm1);
        m0 = nm0; m1 = nm1;
        float sum0 = 0.f, sum1 = 0.f;
#pragma unroll
        for (int ni = 0; ni < 8; ni++) {
            s[ni][0] = fexp2(s[ni][0] - nm0);
            s[ni][1] = fexp2(s[ni][1] - nm0);
            s[ni][2] = fexp2(s[ni][2] - nm1);
            s[ni][3] = fexp2(s[ni][3] - nm1);
            sum0 += s[ni][0] + s[ni][1];
            sum1 += s[ni][2] + s[ni][3];
        }
        sum0 += __shfl_xor_sync(0xffffffffu, sum0, 1);
        sum0 += __shfl_xor_sync(0xffffffffu, sum0, 2);
        sum1 += __shfl_xor_sync(0xffffffffu, sum1, 1);
        sum1 += __shfl_xor_sync(0xffffffffu, sum1, 2);
        l0 = l0 * a0 + sum0;
        l1 = l1 * a1 + sum1;
#pragma unroll
        for (int di = 0; di < 8; di++) {
            o[di][0] *= a0; o[di][1] *= a0;
            o[di][2] *= a1; o[di][3] *= a1;
        }

#pragma unroll
        for (int kj = 0; kj < 4; kj++) {
            uint32_t a[4];
            a[0] = h2u(s[2*kj][0],   s[2*kj][1]);
            a[1] = h2u(s[2*kj][2],   s[2*kj][3]);
            a[2] = h2u(s[2*kj+1][0], s[2*kj+1][1]);
            a[3] = h2u(s[2*kj+1][2], s[2*kj+1][3]);
#pragma unroll
            for (int p = 0; p < 4; p++) {
                uint32_t bf[4];
                ldsm4t(bf, vbase + ((kj*16 + (m4 & 1)*8 + l7) * AP + (p*2 + (m4 >> 1)) * 8) * 2);
                mma16(o[2*p],   a, bf);
                mma16(o[2*p+1], a, bf + 2);
            }
        }
        __syncthreads();
    }

    float i0 = 1.0f / l0, i1 = 1.0f / l1;
    int gr = tokQ + rloc;
#pragma unroll
    for (int di = 0; di < 8; di++) {
        int c = di*8 + 2*(lane & 3);
        *(__half2*)&O[(size_t)gr * (NH*HD) + h*HD + c] =
            __floats2half2_rn(o[di][0] * i0, o[di][1] * i0);
        *(__half2*)&O[(size_t)(gr + 8) * (NH*HD) + h*HD + c] =
            __floats2half2_rn(o[di][2] * i1, o[di][3] * i1);
    }
}

__global__ void __launch_bounds__(128) attn_kernel(
    const __half* __restrict__ Q, const __half* __restrict__ K,
    const __half* __restrict__ V, __half* __restrict__ O)
{
    extern __shared__ __half sh[];
    uint32_t smb = cvta_smem(sh);
    const int bh = blockIdx.y;
    const int b  = bh / NH, h = bh % NH, kvh = h / NGRP;
    attn_tile(Q, K, V, O, smb, blockIdx.x,           b, h, kvh);
    __syncthreads();
    attn_tile(Q, K, V, O, smb, NQT - 1 - blockIdx.x, b, h, kvh);
}

// ---------------- launch ----------------------------------------------------
extern "C" void kernel_launch(void* const* d_in, const int* in_sizes, int n_in,
                              void* d_out, int out_size) {
    const float* X  = (const float*)d_in[0];
    // d_in[1] = attention_mask: fixed causal mask -> analytic
    const float* Wq = (const float*)d_in[2];
    const float* bq = (const float*)d_in[3];
    const float* Wk = (const float*)d_in[4];
    const float* bk = (const float*)d_in[5];
    const float* Wv = (const float*)d_in[6];
    const float* bv = (const float*)d_in[7];
    const float* Wo = (const float*)d_in[8];
    float* out = (float*)d_out;

    __half *xh, *q, *k, *v, *att, *wq, *wk, *wv, *wo;
    float *zb;
    cudaGetSymbolAddress((void**)&xh,  g_xh);
    cudaGetSymbolAddress((void**)&q,   g_q);
    cudaGetSymbolAddress((void**)&k,   g_k);
    cudaGetSymbolAddress((void**)&v,   g_v);
    cudaGetSymbolAddress((void**)&att, g_att);
    cudaGetSymbolAddress((void**)&wq,  g_wq);
    cudaGetSymbolAddress((void**)&wk,  g_wk);
    cudaGetSymbolAddress((void**)&wv,  g_wv);
    cudaGetSymbolAddress((void**)&wo,  g_wo);
    cudaGetSymbolAddress((void**)&zb,  g_zero);

    // prep
    conv_x_kernel<<<(NTOK*HID + 255)/256, 256>>>(X, xh, NTOK*HID);
    conv_wT_all<<<dim3(KD/32, HID/32, 4), dim3(32,8)>>>(Wq, Wk, Wv, Wo, wq, wk, wv, wo);

    // fused QKV projection + RoPE epilogue (64-row M tiles: 576 CTAs)
    gemm_qkv_kernel<<<dim3(9, NTOK/64), 256>>>(xh, wq, wk, wv, bq, bk, bv, q, k, v);

    // attention (pair-balanced, register-P)
    cudaFuncSetAttribute(attn_kernel, cudaFuncAttributeMaxDynamicSharedMemorySize, ATT_SMEM);
    attn_kernel<<<dim3(NQT/2, BATCH*NH), 128, ATT_SMEM>>>(q, k, v, att);

    // output projection (64-row M tiles: 448 CTAs)
    gemm_o_kernel<<<dim3(HID/128, NTOK/64), 256>>>(att, wo, zb, out);
}